// round 13
// baseline (speedup 1.0000x reference)
#include <cuda_runtime.h>
#include <cuda_bf16.h>
#include <cstdint>
#include <cstring>
#include <math.h>

#define MAXS 24576

__device__ int   d_segstart[MAXS + 1];
__device__ float d_gsum[MAXS];
__device__ __nv_bfloat16 d_ph[(size_t)MAXS * 256];   // pooled hi (bf16 split)
__device__ __nv_bfloat16 d_pl[(size_t)MAXS * 256];   // pooled lo
__device__ __nv_bfloat16 d_Wth[256 * 256];           // Wm^T hi  [n][k]
__device__ __nv_bfloat16 d_Wtl[256 * 256];           // Wm^T lo

__device__ __forceinline__ float ex2f(float x) {
    float y; asm("ex2.approx.ftz.f32 %0, %1;" : "=f"(y) : "f"(x)); return y;
}
__device__ __forceinline__ float lg2f(float x) {
    float y; asm("lg2.approx.ftz.f32 %0, %1;" : "=f"(y) : "f"(x)); return y;
}
#define L2E 1.4426950408889634f

// ---------------------------------------------------------------------------
// Kernel 1: segment boundaries (index sorted), 4 nodes per thread.
// ---------------------------------------------------------------------------
__global__ void seg_bounds_kernel(const int* __restrict__ index, int N, int S) {
    int base = (blockIdx.x * blockDim.x + threadIdx.x) * 4;
    if (base >= N) return;
    int prev = (base == 0) ? -1 : index[base - 1];
    int v[4];
    if (base + 3 < N) {
        int4 q = *(const int4*)&index[base];
        v[0] = q.x; v[1] = q.y; v[2] = q.z; v[3] = q.w;
    } else {
        for (int k = 0; k < 4; k++) v[k] = (base + k < N) ? index[base + k] : 0;
    }
    #pragma unroll
    for (int k = 0; k < 4; k++) {
        int n = base + k;
        if (n < N) {
            for (int s = prev + 1; s <= v[k]; s++) d_segstart[s] = n;
            prev = v[k];
            if (n == N - 1)
                for (int s = v[k] + 1; s <= S; s++) d_segstart[s] = N;
        }
    }
}

// ---------------------------------------------------------------------------
// Kernel 2: prep — transpose + bf16-split Wm into Wt[n][k] (hi/lo).
// ---------------------------------------------------------------------------
__global__ void prep_kernel(const float* __restrict__ Wm) {
    __shared__ float tile[32][33];
    const int k0 = blockIdx.y * 32, n0 = blockIdx.x * 32;
    for (int r = threadIdx.y; r < 32; r += 8)
        tile[r][threadIdx.x] = Wm[(size_t)(k0 + r) * 256 + n0 + threadIdx.x];
    __syncthreads();
    for (int r = threadIdx.y; r < 32; r += 8) {
        float v = tile[threadIdx.x][r];
        __nv_bfloat16 h = __float2bfloat16(v);
        __nv_bfloat16 l = __float2bfloat16(v - __bfloat162float(h));
        size_t o = (size_t)(n0 + r) * 256 + k0 + threadIdx.x;
        d_Wth[o] = h;
        d_Wtl[o] = l;
    }
}

// ---------------------------------------------------------------------------
// Kernel 3: pooling — one warp per segment (range [s0, sEnd)), online softmax.
// ---------------------------------------------------------------------------
__global__ __launch_bounds__(256) void pool_kernel(
    const float* __restrict__ x,
    const float* __restrict__ wts,
    const float* __restrict__ Wg,
    const float* __restrict__ bg,
    const float* __restrict__ p,
    int s0, int sEnd)
{
    const int s = s0 + blockIdx.x * 8 + (threadIdx.x >> 5);
    if (s >= sEnd) return;
    const int lane = threadIdx.x & 31;

    const float4* __restrict__ x4 = (const float4*)x;
    const float4 wg0 = ((const float4*)Wg)[lane];
    const float4 wg1 = ((const float4*)Wg)[lane + 32];
    const float bg0 = bg[0];
    const float p0  = p[0];

    const int beg = d_segstart[s];
    const int cnt = d_segstart[s + 1] - beg;

    float4 a0 = make_float4(0.f, 0.f, 0.f, 0.f);
    float4 a1 = make_float4(0.f, 0.f, 0.f, 0.f);
    float m = -INFINITY, den = 0.0f;

    float4 c0 = make_float4(0.f, 0.f, 0.f, 0.f);
    float4 c1 = make_float4(0.f, 0.f, 0.f, 0.f);
    float cw = 1.0f;
    if (cnt > 0) {
        size_t b = (size_t)beg * 64;
        c0 = x4[b + lane];
        c1 = x4[b + 32 + lane];
        cw = wts[beg];
    }

    for (int i = 0; i < cnt; i++) {
        float4 n0v = make_float4(0.f, 0.f, 0.f, 0.f);
        float4 n1v = make_float4(0.f, 0.f, 0.f, 0.f);
        float nw = 1.0f;
        if (i + 1 < cnt) {
            size_t b = (size_t)(beg + i + 1) * 64;
            n0v = x4[b + lane];
            n1v = x4[b + 32 + lane];
            nw = wts[beg + i + 1];
        }

        float dot = c0.x * wg0.x + c0.y * wg0.y + c0.z * wg0.z + c0.w * wg0.w
                  + c1.x * wg1.x + c1.y * wg1.y + c1.z * wg1.z + c1.w * wg1.w;
        #pragma unroll
        for (int o = 16; o; o >>= 1)
            dot += __shfl_xor_sync(0xffffffffu, dot, o);
        const float lg = dot + bg0;

        const float nm = fmaxf(m, lg);
        const float sc = ex2f((m - nm) * L2E);
        const float e  = ex2f(fmaf(p0, lg2f(cw), (lg - nm) * L2E));
        den = den * sc + e;
        a0.x = fmaf(e, c0.x, a0.x * sc);
        a0.y = fmaf(e, c0.y, a0.y * sc);
        a0.z = fmaf(e, c0.z, a0.z * sc);
        a0.w = fmaf(e, c0.w, a0.w * sc);
        a1.x = fmaf(e, c1.x, a1.x * sc);
        a1.y = fmaf(e, c1.y, a1.y * sc);
        a1.z = fmaf(e, c1.z, a1.z * sc);
        a1.w = fmaf(e, c1.w, a1.w * sc);
        m = nm;

        c0 = n0v; c1 = n1v; cw = nw;
    }

    const float inv = 1.0f / (den + 1e-10f);
    float4 r0, r1;
    r0.x = a0.x * inv; r0.y = a0.y * inv; r0.z = a0.z * inv; r0.w = a0.w * inv;
    r1.x = a1.x * inv; r1.y = a1.y * inv; r1.z = a1.z * inv; r1.w = a1.w * inv;

    {
        __nv_bfloat162 h01 = __floats2bfloat162_rn(r0.x, r0.y);
        __nv_bfloat162 h23 = __floats2bfloat162_rn(r0.z, r0.w);
        __nv_bfloat162 l01 = __floats2bfloat162_rn(r0.x - __bfloat162float(h01.x),
                                                   r0.y - __bfloat162float(h01.y));
        __nv_bfloat162 l23 = __floats2bfloat162_rn(r0.z - __bfloat162float(h23.x),
                                                   r0.w - __bfloat162float(h23.y));
        size_t o = (size_t)s * 256 + 4 * lane;
        uint2 uh, ul;
        memcpy(&uh.x, &h01, 4); memcpy(&uh.y, &h23, 4);
        memcpy(&ul.x, &l01, 4); memcpy(&ul.y, &l23, 4);
        *(uint2*)&d_ph[o] = uh;
        *(uint2*)&d_pl[o] = ul;
    }
    {
        __nv_bfloat162 h01 = __floats2bfloat162_rn(r1.x, r1.y);
        __nv_bfloat162 h23 = __floats2bfloat162_rn(r1.z, r1.w);
        __nv_bfloat162 l01 = __floats2bfloat162_rn(r1.x - __bfloat162float(h01.x),
                                                   r1.y - __bfloat162float(h01.y));
        __nv_bfloat162 l23 = __floats2bfloat162_rn(r1.z - __bfloat162float(h23.x),
                                                   r1.w - __bfloat162float(h23.y));
        size_t o = (size_t)s * 256 + 128 + 4 * lane;
        uint2 uh, ul;
        memcpy(&uh.x, &h01, 4); memcpy(&uh.y, &h23, 4);
        memcpy(&ul.x, &l01, 4); memcpy(&ul.y, &l23, 4);
        *(uint2*)&d_ph[o] = uh;
        *(uint2*)&d_pl[o] = ul;
    }
    if (lane == 0) d_gsum[s] = den * inv;
}

// ---------------------------------------------------------------------------
// Kernel 4: split-bf16 HMMA GEMM (R8 config, 2-stage cp.async, m-chunked).
// Block tile 128x64 (512 thr, 4x4 warp grid, warp tile 32x16), 2 CTAs/SM.
// ---------------------------------------------------------------------------
#define GM 128
#define GN 64
#define AK 40                       // bf16 per padded smem row (32 + 8)
#define A_TILE (128 * AK * 2)       // 10240 B
#define B_TILE (64 * AK * 2)        // 5120 B
#define STAGE  (2 * A_TILE + 2 * B_TILE)   // 30720 B
// within a stage: Ah @0, Al @A_TILE, Bh @2*A_TILE, Bl @2*A_TILE+B_TILE

#define MMA_BF16(d, a, b)                                                     \
    asm volatile(                                                             \
        "mma.sync.aligned.m16n8k16.row.col.f32.bf16.bf16.f32 "                \
        "{%0,%1,%2,%3}, {%4,%5,%6,%7}, {%8,%9}, {%0,%1,%2,%3};"               \
        : "+f"((d)[0]), "+f"((d)[1]), "+f"((d)[2]), "+f"((d)[3])              \
        : "r"((a)[0]), "r"((a)[1]), "r"((a)[2]), "r"((a)[3]),                 \
          "r"((b)[0]), "r"((b)[1]))

__device__ __forceinline__ void ldsm_x4(unsigned& r0, unsigned& r1,
                                        unsigned& r2, unsigned& r3,
                                        unsigned addr) {
    asm volatile("ldmatrix.sync.aligned.m8n8.x4.shared.b16 {%0,%1,%2,%3}, [%4];"
                 : "=r"(r0), "=r"(r1), "=r"(r2), "=r"(r3) : "r"(addr));
}
__device__ __forceinline__ void cp16(unsigned dst, const void* src, int sz) {
    asm volatile("cp.async.cg.shared.global [%0], [%1], 16, %2;"
                 :: "r"(dst), "l"(src), "r"(sz));
}

__global__ __launch_bounds__(512, 2) void gemm_mma_kernel(
    const float* __restrict__ bm,
    float* __restrict__ out,
    int S, int mbase)
{
    extern __shared__ char smem[];
    const unsigned sbase = (unsigned)__cvta_generic_to_shared(smem);

    const int tid  = threadIdx.x;
    const int warp = tid >> 5, lane = tid & 31;
    const int g = lane >> 2, t = lane & 3;
    const int wm = warp >> 2;          // 0..3 (M)
    const int wn = warp & 3;           // 0..3 (N)
    const int m0 = mbase + blockIdx.x * GM;
    const int n0 = blockIdx.y * GN;

    float acc[2][2][4] = {};           // [m16 tile][n8 frag][regs]

    // ---- loader mapping ----
    const int lrow = tid >> 2;         // 0..127
    const int lchk = tid & 3;          // 0..3
    int arow = m0 + lrow;
    const int asz = (arow < S) ? 16 : 0;
    if (arow >= S) arow = 0;
    const unsigned a_dst = (unsigned)(lrow * (AK * 2) + lchk * 16);
    const int b_hl  = tid >> 8;
    const int b_row = (tid & 255) >> 2;
    const int b_chk = tid & 3;
    const unsigned b_dst = (unsigned)(2 * A_TILE + b_hl * B_TILE
                                      + b_row * (AK * 2) + b_chk * 16);
    const __nv_bfloat16* __restrict__ bsrc = b_hl ? d_Wtl : d_Wth;

    // ---- ldmatrix per-lane invariant offsets (bytes) ----
    unsigned a_off[2];
    #pragma unroll
    for (int i = 0; i < 2; i++)
        a_off[i] = (unsigned)((wm * 32 + i * 16 + (lane & 15)) * (AK * 2)
                              + (lane >> 4) * 16);
    const unsigned b_off =
        (unsigned)((wn * 16 + ((lane >> 4) << 3) + (lane & 7)) * (AK * 2)
                   + (((lane >> 3) & 1) << 4));

    auto load_stage = [&](int it) {
        const int kb = it * 32;
        const unsigned sb = sbase + (unsigned)((it & 1) * STAGE);
        cp16(sb + a_dst,          &d_ph[(size_t)arow * 256 + kb + lchk * 8], asz);
        cp16(sb + A_TILE + a_dst, &d_pl[(size_t)arow * 256 + kb + lchk * 8], asz);
        cp16(sb + b_dst, &bsrc[(size_t)(n0 + b_row) * 256 + kb + b_chk * 8], 16);
        asm volatile("cp.async.commit_group;");
    };

    load_stage(0);
    load_stage(1);

    #pragma unroll
    for (int it = 0; it < 8; it++) {
        if (it < 6) asm volatile("cp.async.wait_group 1;");
        else        asm volatile("cp.async.wait_group 0;");
        __syncthreads();

        const unsigned sb = sbase + (unsigned)((it & 1) * STAGE);

        #pragma unroll
        for (int kk = 0; kk < 2; kk++) {
            const unsigned kadd = kk * 32;   // 16 bf16 = 32 bytes

            unsigned ah[2][4], al[2][4];
            #pragma unroll
            for (int i = 0; i < 2; i++) {
                ldsm_x4(ah[i][0], ah[i][1], ah[i][2], ah[i][3],
                        sb + a_off[i] + kadd);
                ldsm_x4(al[i][0], al[i][1], al[i][2], al[i][3],
                        sb + A_TILE + a_off[i] + kadd);
            }
            unsigned bh[2][2], bl[2][2];
            {
                unsigned r0, r1, r2, r3;
                ldsm_x4(r0, r1, r2, r3, sb + 2 * A_TILE + b_off + kadd);
                bh[0][0] = r0; bh[0][1] = r1; bh[1][0] = r2; bh[1][1] = r3;
                ldsm_x4(r0, r1, r2, r3, sb + 2 * A_TILE + B_TILE + b_off + kadd);
                bl[0][0] = r0; bl[0][1] = r1; bl[1][0] = r2; bl[1][1] = r3;
            }

            #pragma unroll
            for (int i = 0; i < 2; i++)
                #pragma unroll
                for (int j = 0; j < 2; j++) {
                    MMA_BF16(acc[i][j], ah[i], bh[j]);
                    MMA_BF16(acc[i][j], ah[i], bl[j]);
                    MMA_BF16(acc[i][j], al[i], bh[j]);
                }
        }
        __syncthreads();
        if (it + 2 < 8) load_stage(it + 2);
    }

    // ---- epilogue: + gsum[m] * bm[n] ----
    #pragma unroll
    for (int i = 0; i < 2; i++) {
        #pragma unroll
        for (int rr = 0; rr < 2; rr++) {
            const int mrow = m0 + wm * 32 + i * 16 + g + rr * 8;
            if (mrow < S) {
                const float gs = d_gsum[mrow];
                #pragma unroll
                for (int j = 0; j < 2; j++) {
                    const int n = n0 + wn * 16 + j * 8 + 2 * t;
                    float2 o;
                    o.x = acc[i][j][rr * 2 + 0] + gs * bm[n];
                    o.y = acc[i][j][rr * 2 + 1] + gs * bm[n + 1];
                    *(float2*)&out[(size_t)mrow * 256 + n] = o;
                }
            }
        }
    }
}

// ---------------------------------------------------------------------------
// Inputs: x, weights, Wg, bg, Wm, bm, p, index, num_segments
// Launch DAG (fork/join, graph-capturable):
//   main:  seg -> pool[0,S0) -> pool[S0,S)
//   side:  prep -> (wait pool0) gemm[0,S0) -> (wait pool1) gemm[S0,S)
// ---------------------------------------------------------------------------
extern "C" void kernel_launch(void* const* d_in, const int* in_sizes, int n_in,
                              void* d_out, int out_size) {
    const float* x     = (const float*)d_in[0];
    const float* wts   = (const float*)d_in[1];
    const float* Wg    = (const float*)d_in[2];
    const float* bg    = (const float*)d_in[3];
    const float* Wm    = (const float*)d_in[4];
    const float* bm    = (const float*)d_in[5];
    const float* p     = (const float*)d_in[6];
    const int*   index = (const int*)d_in[7];

    const int N = in_sizes[7];
    const int S = out_size / 256;
    const int smem_bytes = 2 * STAGE;   // 61440

    static cudaStream_t s1 = nullptr;
    static cudaEvent_t evFork = nullptr, ev0 = nullptr, ev1 = nullptr, evJ = nullptr;
    if (s1 == nullptr) {
        cudaStreamCreateWithFlags(&s1, cudaStreamNonBlocking);
        cudaEventCreateWithFlags(&evFork, cudaEventDisableTiming);
        cudaEventCreateWithFlags(&ev0,    cudaEventDisableTiming);
        cudaEventCreateWithFlags(&ev1,    cudaEventDisableTiming);
        cudaEventCreateWithFlags(&evJ,    cudaEventDisableTiming);
        cudaFuncSetAttribute(gemm_mma_kernel,
                             cudaFuncAttributeMaxDynamicSharedMemorySize, smem_bytes);
    }

    // split point: ~2/3 of segments, multiple of 128 (gemm tile) and 8 (pool blk)
    int S0 = ((2 * S / 3) / 128) * 128;
    if (S0 <= 0 || S0 >= S) S0 = 0;   // degenerate: single chunk

    seg_bounds_kernel<<<(N / 4 + 256) / 256, 256>>>(index, N, S);

    cudaEventRecord(evFork, 0);
    cudaStreamWaitEvent(s1, evFork, 0);
    prep_kernel<<<dim3(8, 8), dim3(32, 8), 0, s1>>>(Wm);

    if (S0 > 0) {
        pool_kernel<<<S0 / 8, 256>>>(x, wts, Wg, bg, p, 0, S0);
        cudaEventRecord(ev0, 0);
        pool_kernel<<<(S - S0 + 7) / 8, 256>>>(x, wts, Wg, bg, p, S0, S);
        cudaEventRecord(ev1, 0);

        cudaStreamWaitEvent(s1, ev0, 0);
        gemm_mma_kernel<<<dim3(S0 / GM, 256 / GN), 512, smem_bytes, s1>>>(
            bm, (float*)d_out, S, 0);
        cudaStreamWaitEvent(s1, ev1, 0);
        gemm_mma_kernel<<<dim3((S - S0 + GM - 1) / GM, 256 / GN), 512, smem_bytes, s1>>>(
            bm, (float*)d_out, S, S0);
    } else {
        pool_kernel<<<(S + 7) / 8, 256>>>(x, wts, Wg, bg, p, 0, S);
        cudaEventRecord(ev0, 0);
        cudaStreamWaitEvent(s1, ev0, 0);
        gemm_mma_kernel<<<dim3((S + GM - 1) / GM, 256 / GN), 512, smem_bytes, s1>>>(
            bm, (float*)d_out, S, 0);
    }

    cudaEventRecord(evJ, s1);
    cudaStreamWaitEvent(0, evJ, 0);
}

// round 14
// speedup vs baseline: 1.0715x; 1.0715x over previous
#include <cuda_runtime.h>
#include <cuda_bf16.h>
#include <cstdint>
#include <cstring>
#include <math.h>

#define MAXS 24576

__device__ int   d_segstart[MAXS + 1];
__device__ float d_gsum[MAXS];
__device__ __nv_bfloat16 d_ph[(size_t)MAXS * 256];   // pooled hi (bf16 split)
__device__ __nv_bfloat16 d_pl[(size_t)MAXS * 256];   // pooled lo
__device__ __nv_bfloat16 d_Wth[256 * 256];           // Wm^T hi  [n][k]
__device__ __nv_bfloat16 d_Wtl[256 * 256];           // Wm^T lo

__device__ __forceinline__ float ex2f(float x) {
    float y; asm("ex2.approx.ftz.f32 %0, %1;" : "=f"(y) : "f"(x)); return y;
}
__device__ __forceinline__ float lg2f(float x) {
    float y; asm("lg2.approx.ftz.f32 %0, %1;" : "=f"(y) : "f"(x)); return y;
}
#define L2E 1.4426950408889634f

// ---------------------------------------------------------------------------
// Kernel 1: fused segment-bounds (index sorted) + Wm transpose/split prep.
// Blocks [0, segBlocks) do bounds; blocks [segBlocks, segBlocks+64) do prep.
// ---------------------------------------------------------------------------
__global__ void setup_kernel(const int* __restrict__ index,
                             const float* __restrict__ Wm,
                             int N, int S, int segBlocks) {
    if ((int)blockIdx.x >= segBlocks) {
        // ---- prep: d_Wt{h,l}[n][k] = split(Wm[k][n]) ----
        __shared__ float tile[32][33];
        const int id = blockIdx.x - segBlocks;      // 0..63
        const int n0 = (id & 7) * 32, k0 = (id >> 3) * 32;
        const int tx = threadIdx.x & 31, ty = threadIdx.x >> 5;
        for (int r = ty; r < 32; r += 8)
            tile[r][tx] = Wm[(size_t)(k0 + r) * 256 + n0 + tx];
        __syncthreads();
        for (int r = ty; r < 32; r += 8) {
            float v = tile[tx][r];
            __nv_bfloat16 h = __float2bfloat16(v);
            __nv_bfloat16 l = __float2bfloat16(v - __bfloat162float(h));
            size_t o = (size_t)(n0 + r) * 256 + k0 + tx;
            d_Wth[o] = h;
            d_Wtl[o] = l;
        }
        return;
    }

    int base = (blockIdx.x * blockDim.x + threadIdx.x) * 4;
    if (base >= N) return;
    int prev = (base == 0) ? -1 : index[base - 1];
    int v[4];
    if (base + 3 < N) {
        int4 q = *(const int4*)&index[base];
        v[0] = q.x; v[1] = q.y; v[2] = q.z; v[3] = q.w;
    } else {
        for (int k = 0; k < 4; k++) v[k] = (base + k < N) ? index[base + k] : 0;
    }
    #pragma unroll
    for (int k = 0; k < 4; k++) {
        int n = base + k;
        if (n < N) {
            for (int s = prev + 1; s <= v[k]; s++) d_segstart[s] = n;
            prev = v[k];
            if (n == N - 1)
                for (int s = v[k] + 1; s <= S; s++) d_segstart[s] = N;
        }
    }
}

// ---------------------------------------------------------------------------
// Kernel 2: pooling — one warp per segment, online softmax, registers only.
// 128-thread blocks (4 warps) for finer scheduling granularity / less
// straggler waste; 8 blocks co-resident per SM.
// ---------------------------------------------------------------------------
__global__ __launch_bounds__(128) void pool_kernel(
    const float* __restrict__ x,
    const float* __restrict__ wts,
    const float* __restrict__ Wg,
    const float* __restrict__ bg,
    const float* __restrict__ p,
    int S)
{
    const int s = blockIdx.x * 4 + (threadIdx.x >> 5);
    if (s >= S) return;
    const int lane = threadIdx.x & 31;

    const float4* __restrict__ x4 = (const float4*)x;
    const float4 wg0 = ((const float4*)Wg)[lane];
    const float4 wg1 = ((const float4*)Wg)[lane + 32];
    const float bg0 = bg[0];
    const float p0  = p[0];

    const int beg = d_segstart[s];
    const int cnt = d_segstart[s + 1] - beg;

    float4 a0 = make_float4(0.f, 0.f, 0.f, 0.f);
    float4 a1 = make_float4(0.f, 0.f, 0.f, 0.f);
    float m = -INFINITY, den = 0.0f;

    float4 c0 = make_float4(0.f, 0.f, 0.f, 0.f);
    float4 c1 = make_float4(0.f, 0.f, 0.f, 0.f);
    float cw = 1.0f;
    if (cnt > 0) {
        size_t b = (size_t)beg * 64;
        c0 = x4[b + lane];
        c1 = x4[b + 32 + lane];
        cw = wts[beg];
    }

    for (int i = 0; i < cnt; i++) {
        float4 n0v = make_float4(0.f, 0.f, 0.f, 0.f);
        float4 n1v = make_float4(0.f, 0.f, 0.f, 0.f);
        float nw = 1.0f;
        if (i + 1 < cnt) {
            size_t b = (size_t)(beg + i + 1) * 64;
            n0v = x4[b + lane];
            n1v = x4[b + 32 + lane];
            nw = wts[beg + i + 1];
        }

        float dot = c0.x * wg0.x + c0.y * wg0.y + c0.z * wg0.z + c0.w * wg0.w
                  + c1.x * wg1.x + c1.y * wg1.y + c1.z * wg1.z + c1.w * wg1.w;
        #pragma unroll
        for (int o = 16; o; o >>= 1)
            dot += __shfl_xor_sync(0xffffffffu, dot, o);
        const float lg = dot + bg0;

        const float nm = fmaxf(m, lg);
        const float sc = ex2f((m - nm) * L2E);
        const float e  = ex2f(fmaf(p0, lg2f(cw), (lg - nm) * L2E));
        den = den * sc + e;
        a0.x = fmaf(e, c0.x, a0.x * sc);
        a0.y = fmaf(e, c0.y, a0.y * sc);
        a0.z = fmaf(e, c0.z, a0.z * sc);
        a0.w = fmaf(e, c0.w, a0.w * sc);
        a1.x = fmaf(e, c1.x, a1.x * sc);
        a1.y = fmaf(e, c1.y, a1.y * sc);
        a1.z = fmaf(e, c1.z, a1.z * sc);
        a1.w = fmaf(e, c1.w, a1.w * sc);
        m = nm;

        c0 = n0v; c1 = n1v; cw = nw;
    }

    const float inv = 1.0f / (den + 1e-10f);
    float4 r0, r1;
    r0.x = a0.x * inv; r0.y = a0.y * inv; r0.z = a0.z * inv; r0.w = a0.w * inv;
    r1.x = a1.x * inv; r1.y = a1.y * inv; r1.z = a1.z * inv; r1.w = a1.w * inv;

    {
        __nv_bfloat162 h01 = __floats2bfloat162_rn(r0.x, r0.y);
        __nv_bfloat162 h23 = __floats2bfloat162_rn(r0.z, r0.w);
        __nv_bfloat162 l01 = __floats2bfloat162_rn(r0.x - __bfloat162float(h01.x),
                                                   r0.y - __bfloat162float(h01.y));
        __nv_bfloat162 l23 = __floats2bfloat162_rn(r0.z - __bfloat162float(h23.x),
                                                   r0.w - __bfloat162float(h23.y));
        size_t o = (size_t)s * 256 + 4 * lane;
        uint2 uh, ul;
        memcpy(&uh.x, &h01, 4); memcpy(&uh.y, &h23, 4);
        memcpy(&ul.x, &l01, 4); memcpy(&ul.y, &l23, 4);
        *(uint2*)&d_ph[o] = uh;
        *(uint2*)&d_pl[o] = ul;
    }
    {
        __nv_bfloat162 h01 = __floats2bfloat162_rn(r1.x, r1.y);
        __nv_bfloat162 h23 = __floats2bfloat162_rn(r1.z, r1.w);
        __nv_bfloat162 l01 = __floats2bfloat162_rn(r1.x - __bfloat162float(h01.x),
                                                   r1.y - __bfloat162float(h01.y));
        __nv_bfloat162 l23 = __floats2bfloat162_rn(r1.z - __bfloat162float(h23.x),
                                                   r1.w - __bfloat162float(h23.y));
        size_t o = (size_t)s * 256 + 128 + 4 * lane;
        uint2 uh, ul;
        memcpy(&uh.x, &h01, 4); memcpy(&uh.y, &h23, 4);
        memcpy(&ul.x, &l01, 4); memcpy(&ul.y, &l23, 4);
        *(uint2*)&d_ph[o] = uh;
        *(uint2*)&d_pl[o] = ul;
    }
    if (lane == 0) d_gsum[s] = den * inv;
}

// ---------------------------------------------------------------------------
// Kernel 3: split-bf16 HMMA GEMM (R8 config: 128x64, 512 thr, 2-stage,
// 2 CTAs/SM) — unchanged from the best-known configuration.
// ---------------------------------------------------------------------------
#define GM 128
#define GN 64
#define AK 40                       // bf16 per padded smem row (32 + 8)
#define A_TILE (128 * AK * 2)       // 10240 B
#define B_TILE (64 * AK * 2)        // 5120 B
#define STAGE  (2 * A_TILE + 2 * B_TILE)   // 30720 B
// within a stage: Ah @0, Al @A_TILE, Bh @2*A_TILE, Bl @2*A_TILE+B_TILE

#define MMA_BF16(d, a, b)                                                     \
    asm volatile(                                                             \
        "mma.sync.aligned.m16n8k16.row.col.f32.bf16.bf16.f32 "                \
        "{%0,%1,%2,%3}, {%4,%5,%6,%7}, {%8,%9}, {%0,%1,%2,%3};"               \
        : "+f"((d)[0]), "+f"((d)[1]), "+f"((d)[2]), "+f"((d)[3])              \
        : "r"((a)[0]), "r"((a)[1]), "r"((a)[2]), "r"((a)[3]),                 \
          "r"((b)[0]), "r"((b)[1]))

__device__ __forceinline__ void ldsm_x4(unsigned& r0, unsigned& r1,
                                        unsigned& r2, unsigned& r3,
                                        unsigned addr) {
    asm volatile("ldmatrix.sync.aligned.m8n8.x4.shared.b16 {%0,%1,%2,%3}, [%4];"
                 : "=r"(r0), "=r"(r1), "=r"(r2), "=r"(r3) : "r"(addr));
}
__device__ __forceinline__ void cp16(unsigned dst, const void* src, int sz) {
    asm volatile("cp.async.cg.shared.global [%0], [%1], 16, %2;"
                 :: "r"(dst), "l"(src), "r"(sz));
}

__global__ __launch_bounds__(512, 2) void gemm_mma_kernel(
    const float* __restrict__ bm,
    float* __restrict__ out,
    int S)
{
    extern __shared__ char smem[];
    const unsigned sbase = (unsigned)__cvta_generic_to_shared(smem);

    const int tid  = threadIdx.x;
    const int warp = tid >> 5, lane = tid & 31;
    const int g = lane >> 2, t = lane & 3;
    const int wm = warp >> 2;          // 0..3 (M)
    const int wn = warp & 3;           // 0..3 (N)
    const int m0 = blockIdx.x * GM;
    const int n0 = blockIdx.y * GN;

    float acc[2][2][4] = {};           // [m16 tile][n8 frag][regs]

    // ---- loader mapping ----
    const int lrow = tid >> 2;         // 0..127
    const int lchk = tid & 3;          // 0..3
    int arow = m0 + lrow;
    const int asz = (arow < S) ? 16 : 0;
    if (arow >= S) arow = 0;
    const unsigned a_dst = (unsigned)(lrow * (AK * 2) + lchk * 16);
    const int b_hl  = tid >> 8;
    const int b_row = (tid & 255) >> 2;
    const int b_chk = tid & 3;
    const unsigned b_dst = (unsigned)(2 * A_TILE + b_hl * B_TILE
                                      + b_row * (AK * 2) + b_chk * 16);
    const __nv_bfloat16* __restrict__ bsrc = b_hl ? d_Wtl : d_Wth;

    // ---- ldmatrix per-lane invariant offsets (bytes) ----
    unsigned a_off[2];
    #pragma unroll
    for (int i = 0; i < 2; i++)
        a_off[i] = (unsigned)((wm * 32 + i * 16 + (lane & 15)) * (AK * 2)
                              + (lane >> 4) * 16);
    const unsigned b_off =
        (unsigned)((wn * 16 + ((lane >> 4) << 3) + (lane & 7)) * (AK * 2)
                   + (((lane >> 3) & 1) << 4));

    auto load_stage = [&](int it) {
        const int kb = it * 32;
        const unsigned sb = sbase + (unsigned)((it & 1) * STAGE);
        cp16(sb + a_dst,          &d_ph[(size_t)arow * 256 + kb + lchk * 8], asz);
        cp16(sb + A_TILE + a_dst, &d_pl[(size_t)arow * 256 + kb + lchk * 8], asz);
        cp16(sb + b_dst, &bsrc[(size_t)(n0 + b_row) * 256 + kb + b_chk * 8], 16);
        asm volatile("cp.async.commit_group;");
    };

    load_stage(0);
    load_stage(1);

    #pragma unroll
    for (int it = 0; it < 8; it++) {
        if (it < 6) asm volatile("cp.async.wait_group 1;");
        else        asm volatile("cp.async.wait_group 0;");
        __syncthreads();

        const unsigned sb = sbase + (unsigned)((it & 1) * STAGE);

        #pragma unroll
        for (int kk = 0; kk < 2; kk++) {
            const unsigned kadd = kk * 32;   // 16 bf16 = 32 bytes

            unsigned ah[2][4], al[2][4];
            #pragma unroll
            for (int i = 0; i < 2; i++) {
                ldsm_x4(ah[i][0], ah[i][1], ah[i][2], ah[i][3],
                        sb + a_off[i] + kadd);
                ldsm_x4(al[i][0], al[i][1], al[i][2], al[i][3],
                        sb + A_TILE + a_off[i] + kadd);
            }
            unsigned bh[2][2], bl[2][2];
            {
                unsigned r0, r1, r2, r3;
                ldsm_x4(r0, r1, r2, r3, sb + 2 * A_TILE + b_off + kadd);
                bh[0][0] = r0; bh[0][1] = r1; bh[1][0] = r2; bh[1][1] = r3;
                ldsm_x4(r0, r1, r2, r3, sb + 2 * A_TILE + B_TILE + b_off + kadd);
                bl[0][0] = r0; bl[0][1] = r1; bl[1][0] = r2; bl[1][1] = r3;
            }

            #pragma unroll
            for (int i = 0; i < 2; i++)
                #pragma unroll
                for (int j = 0; j < 2; j++) {
                    MMA_BF16(acc[i][j], ah[i], bh[j]);
                    MMA_BF16(acc[i][j], ah[i], bl[j]);
                    MMA_BF16(acc[i][j], al[i], bh[j]);
                }
        }
        __syncthreads();
        if (it + 2 < 8) load_stage(it + 2);
    }

    // ---- epilogue: + gsum[m] * bm[n] ----
    #pragma unroll
    for (int i = 0; i < 2; i++) {
        #pragma unroll
        for (int rr = 0; rr < 2; rr++) {
            const int mrow = m0 + wm * 32 + i * 16 + g + rr * 8;
            if (mrow < S) {
                const float gs = d_gsum[mrow];
                #pragma unroll
                for (int j = 0; j < 2; j++) {
                    const int n = n0 + wn * 16 + j * 8 + 2 * t;
                    float2 o;
                    o.x = acc[i][j][rr * 2 + 0] + gs * bm[n];
                    o.y = acc[i][j][rr * 2 + 1] + gs * bm[n + 1];
                    *(float2*)&out[(size_t)mrow * 256 + n] = o;
                }
            }
        }
    }
}

// ---------------------------------------------------------------------------
// Inputs: x, weights, Wg, bg, Wm, bm, p, index, num_segments
// ---------------------------------------------------------------------------
extern "C" void kernel_launch(void* const* d_in, const int* in_sizes, int n_in,
                              void* d_out, int out_size) {
    const float* x     = (const float*)d_in[0];
    const float* wts   = (const float*)d_in[1];
    const float* Wg    = (const float*)d_in[2];
    const float* bg    = (const float*)d_in[3];
    const float* Wm    = (const float*)d_in[4];
    const float* bm    = (const float*)d_in[5];
    const float* p     = (const float*)d_in[6];
    const int*   index = (const int*)d_in[7];

    const int N = in_sizes[7];
    const int S = out_size / 256;
    const int smem_bytes = 2 * STAGE;   // 61440

    cudaFuncSetAttribute(gemm_mma_kernel,
                         cudaFuncAttributeMaxDynamicSharedMemorySize, smem_bytes);

    const int segBlocks = (N / 4 + 256) / 256;

    setup_kernel<<<segBlocks + 64, 256>>>(index, Wm, N, S, segBlocks);
    pool_kernel<<<(S + 3) / 4, 128>>>(x, wts, Wg, bg, p, S);
    gemm_mma_kernel<<<dim3((S + GM - 1) / GM, 256 / GN), 512, smem_bytes>>>(
        bm, (float*)d_out, S);
}

// round 15
// speedup vs baseline: 1.0881x; 1.0155x over previous
#include <cuda_runtime.h>
#include <cuda_bf16.h>
#include <cstdint>
#include <cstring>
#include <math.h>

#define MAXS 24576

__device__ int   d_segstart[MAXS + 1];
__device__ float d_gsum[MAXS];
__device__ __nv_bfloat16 d_ph[(size_t)MAXS * 256];   // pooled hi (bf16 split)
__device__ __nv_bfloat16 d_pl[(size_t)MAXS * 256];   // pooled lo
__device__ __nv_bfloat16 d_Wth[256 * 256];           // Wm^T hi  [n][k]
__device__ __nv_bfloat16 d_Wtl[256 * 256];           // Wm^T lo

__device__ __forceinline__ float ex2f(float x) {
    float y; asm("ex2.approx.ftz.f32 %0, %1;" : "=f"(y) : "f"(x)); return y;
}
__device__ __forceinline__ float lg2f(float x) {
    float y; asm("lg2.approx.ftz.f32 %0, %1;" : "=f"(y) : "f"(x)); return y;
}
#define L2E 1.4426950408889634f

// ---------------------------------------------------------------------------
// Kernel 1: fused segment-bounds (index sorted) + Wm transpose/split prep.
// ---------------------------------------------------------------------------
__global__ void setup_kernel(const int* __restrict__ index,
                             const float* __restrict__ Wm,
                             int N, int S, int segBlocks) {
    if ((int)blockIdx.x >= segBlocks) {
        __shared__ float tile[32][33];
        const int id = blockIdx.x - segBlocks;      // 0..63
        const int n0 = (id & 7) * 32, k0 = (id >> 3) * 32;
        const int tx = threadIdx.x & 31, ty = threadIdx.x >> 5;
        for (int r = ty; r < 32; r += 8)
            tile[r][tx] = Wm[(size_t)(k0 + r) * 256 + n0 + tx];
        __syncthreads();
        for (int r = ty; r < 32; r += 8) {
            float v = tile[tx][r];
            __nv_bfloat16 h = __float2bfloat16(v);
            __nv_bfloat16 l = __float2bfloat16(v - __bfloat162float(h));
            size_t o = (size_t)(n0 + r) * 256 + k0 + tx;
            d_Wth[o] = h;
            d_Wtl[o] = l;
        }
        return;
    }

    int base = (blockIdx.x * blockDim.x + threadIdx.x) * 4;
    if (base >= N) return;
    int prev = (base == 0) ? -1 : index[base - 1];
    int v[4];
    if (base + 3 < N) {
        int4 q = *(const int4*)&index[base];
        v[0] = q.x; v[1] = q.y; v[2] = q.z; v[3] = q.w;
    } else {
        for (int k = 0; k < 4; k++) v[k] = (base + k < N) ? index[base + k] : 0;
    }
    #pragma unroll
    for (int k = 0; k < 4; k++) {
        int n = base + k;
        if (n < N) {
            for (int s = prev + 1; s <= v[k]; s++) d_segstart[s] = n;
            prev = v[k];
            if (n == N - 1)
                for (int s = v[k] + 1; s <= S; s++) d_segstart[s] = N;
        }
    }
}

// ---------------------------------------------------------------------------
// Kernel 2: pooling — one warp per segment, TWO rows per iteration.
// The two dot-product shfl chains interleave (latency overlap) and the
// online-softmax update is merged (one rescale, two exps per pair).
// ---------------------------------------------------------------------------
__global__ __launch_bounds__(128) void pool_kernel(
    const float* __restrict__ x,
    const float* __restrict__ wts,
    const float* __restrict__ Wg,
    const float* __restrict__ bg,
    const float* __restrict__ p,
    int S)
{
    const int s = blockIdx.x * 4 + (threadIdx.x >> 5);
    if (s >= S) return;
    const int lane = threadIdx.x & 31;

    const float4* __restrict__ x4 = (const float4*)x;
    const float4 wg0 = ((const float4*)Wg)[lane];
    const float4 wg1 = ((const float4*)Wg)[lane + 32];
    const float bg0 = bg[0];
    const float p0  = p[0];

    const int beg = d_segstart[s];
    const int cnt = d_segstart[s + 1] - beg;

    float4 a0 = make_float4(0.f, 0.f, 0.f, 0.f);
    float4 a1 = make_float4(0.f, 0.f, 0.f, 0.f);
    float m = -INFINITY, den = 0.0f;

    const float4 z4 = make_float4(0.f, 0.f, 0.f, 0.f);
    float4 c0 = z4, c1 = z4, d0 = z4, d1 = z4;
    float cw = 1.0f, dw = 1.0f;
    if (cnt > 0) {
        size_t b = (size_t)beg * 64;
        c0 = x4[b + lane];
        c1 = x4[b + 32 + lane];
        cw = wts[beg];
    }
    if (cnt > 1) {
        size_t b = (size_t)(beg + 1) * 64;
        d0 = x4[b + lane];
        d1 = x4[b + 32 + lane];
        dw = wts[beg + 1];
    }

    for (int i = 0; i < cnt; i += 2) {
        const bool has_d = (i + 1 < cnt);

        // prefetch rows i+2, i+3
        float4 e0 = z4, e1 = z4, f0 = z4, f1 = z4;
        float ew = 1.0f, fw = 1.0f;
        if (i + 2 < cnt) {
            size_t b = (size_t)(beg + i + 2) * 64;
            e0 = x4[b + lane];
            e1 = x4[b + 32 + lane];
            ew = wts[beg + i + 2];
        }
        if (i + 3 < cnt) {
            size_t b = (size_t)(beg + i + 3) * 64;
            f0 = x4[b + lane];
            f1 = x4[b + 32 + lane];
            fw = wts[beg + i + 3];
        }

        // two independent dots
        float dc = c0.x * wg0.x + c0.y * wg0.y + c0.z * wg0.z + c0.w * wg0.w
                 + c1.x * wg1.x + c1.y * wg1.y + c1.z * wg1.z + c1.w * wg1.w;
        float dd = d0.x * wg0.x + d0.y * wg0.y + d0.z * wg0.z + d0.w * wg0.w
                 + d1.x * wg1.x + d1.y * wg1.y + d1.z * wg1.z + d1.w * wg1.w;
        #pragma unroll
        for (int o = 16; o; o >>= 1) {
            dc += __shfl_xor_sync(0xffffffffu, dc, o);
            dd += __shfl_xor_sync(0xffffffffu, dd, o);
        }
        const float lgc = dc + bg0;
        const float lgd = has_d ? (dd + bg0) : -INFINITY;

        // merged online-softmax update (exact)
        const float m2 = fmaxf(m, fmaxf(lgc, lgd));
        const float sc = ex2f((m - m2) * L2E);              // first iter: 0
        const float ec = ex2f(fmaf(p0, lg2f(cw), (lgc - m2) * L2E));
        const float ed = ex2f(fmaf(p0, lg2f(dw), (lgd - m2) * L2E));  // 0 if !has_d
        den = den * sc + ec + ed;
        a0.x = fmaf(ed, d0.x, fmaf(ec, c0.x, a0.x * sc));
        a0.y = fmaf(ed, d0.y, fmaf(ec, c0.y, a0.y * sc));
        a0.z = fmaf(ed, d0.z, fmaf(ec, c0.z, a0.z * sc));
        a0.w = fmaf(ed, d0.w, fmaf(ec, c0.w, a0.w * sc));
        a1.x = fmaf(ed, d1.x, fmaf(ec, c1.x, a1.x * sc));
        a1.y = fmaf(ed, d1.y, fmaf(ec, c1.y, a1.y * sc));
        a1.z = fmaf(ed, d1.z, fmaf(ec, c1.z, a1.z * sc));
        a1.w = fmaf(ed, d1.w, fmaf(ec, c1.w, a1.w * sc));
        m = m2;

        c0 = e0; c1 = e1; cw = ew;
        d0 = f0; d1 = f1; dw = fw;
    }

    const float inv = 1.0f / (den + 1e-10f);
    float4 r0, r1;
    r0.x = a0.x * inv; r0.y = a0.y * inv; r0.z = a0.z * inv; r0.w = a0.w * inv;
    r1.x = a1.x * inv; r1.y = a1.y * inv; r1.z = a1.z * inv; r1.w = a1.w * inv;

    {
        __nv_bfloat162 h01 = __floats2bfloat162_rn(r0.x, r0.y);
        __nv_bfloat162 h23 = __floats2bfloat162_rn(r0.z, r0.w);
        __nv_bfloat162 l01 = __floats2bfloat162_rn(r0.x - __bfloat162float(h01.x),
                                                   r0.y - __bfloat162float(h01.y));
        __nv_bfloat162 l23 = __floats2bfloat162_rn(r0.z - __bfloat162float(h23.x),
                                                   r0.w - __bfloat162float(h23.y));
        size_t o = (size_t)s * 256 + 4 * lane;
        uint2 uh, ul;
        memcpy(&uh.x, &h01, 4); memcpy(&uh.y, &h23, 4);
        memcpy(&ul.x, &l01, 4); memcpy(&ul.y, &l23, 4);
        *(uint2*)&d_ph[o] = uh;
        *(uint2*)&d_pl[o] = ul;
    }
    {
        __nv_bfloat162 h01 = __floats2bfloat162_rn(r1.x, r1.y);
        __nv_bfloat162 h23 = __floats2bfloat162_rn(r1.z, r1.w);
        __nv_bfloat162 l01 = __floats2bfloat162_rn(r1.x - __bfloat162float(h01.x),
                                                   r1.y - __bfloat162float(h01.y));
        __nv_bfloat162 l23 = __floats2bfloat162_rn(r1.z - __bfloat162float(h23.x),
                                                   r1.w - __bfloat162float(h23.y));
        size_t o = (size_t)s * 256 + 128 + 4 * lane;
        uint2 uh, ul;
        memcpy(&uh.x, &h01, 4); memcpy(&uh.y, &h23, 4);
        memcpy(&ul.x, &l01, 4); memcpy(&ul.y, &l23, 4);
        *(uint2*)&d_ph[o] = uh;
        *(uint2*)&d_pl[o] = ul;
    }
    if (lane == 0) d_gsum[s] = den * inv;
}

// ---------------------------------------------------------------------------
// Kernel 3: split-bf16 HMMA GEMM (R8 config: 128x64, 512 thr, 2-stage,
// 2 CTAs/SM) — unchanged.
// ---------------------------------------------------------------------------
#define GM 128
#define GN 64
#define AK 40                       // bf16 per padded smem row (32 + 8)
#define A_TILE (128 * AK * 2)       // 10240 B
#define B_TILE (64 * AK * 2)        // 5120 B
#define STAGE  (2 * A_TILE + 2 * B_TILE)   // 30720 B

#define MMA_BF16(d, a, b)                                                     \
    asm volatile(                                                             \
        "mma.sync.aligned.m16n8k16.row.col.f32.bf16.bf16.f32 "                \
        "{%0,%1,%2,%3}, {%4,%5,%6,%7}, {%8,%9}, {%0,%1,%2,%3};"               \
        : "+f"((d)[0]), "+f"((d)[1]), "+f"((d)[2]), "+f"((d)[3])              \
        : "r"((a)[0]), "r"((a)[1]), "r"((a)[2]), "r"((a)[3]),                 \
          "r"((b)[0]), "r"((b)[1]))

__device__ __forceinline__ void ldsm_x4(unsigned& r0, unsigned& r1,
                                        unsigned& r2, unsigned& r3,
                                        unsigned addr) {
    asm volatile("ldmatrix.sync.aligned.m8n8.x4.shared.b16 {%0,%1,%2,%3}, [%4];"
                 : "=r"(r0), "=r"(r1), "=r"(r2), "=r"(r3) : "r"(addr));
}
__device__ __forceinline__ void cp16(unsigned dst, const void* src, int sz) {
    asm volatile("cp.async.cg.shared.global [%0], [%1], 16, %2;"
                 :: "r"(dst), "l"(src), "r"(sz));
}

__global__ __launch_bounds__(512, 2) void gemm_mma_kernel(
    const float* __restrict__ bm,
    float* __restrict__ out,
    int S)
{
    extern __shared__ char smem[];
    const unsigned sbase = (unsigned)__cvta_generic_to_shared(smem);

    const int tid  = threadIdx.x;
    const int warp = tid >> 5, lane = tid & 31;
    const int g = lane >> 2, t = lane & 3;
    const int wm = warp >> 2;          // 0..3 (M)
    const int wn = warp & 3;           // 0..3 (N)
    const int m0 = blockIdx.x * GM;
    const int n0 = blockIdx.y * GN;

    float acc[2][2][4] = {};

    const int lrow = tid >> 2;
    const int lchk = tid & 3;
    int arow = m0 + lrow;
    const int asz = (arow < S) ? 16 : 0;
    if (arow >= S) arow = 0;
    const unsigned a_dst = (unsigned)(lrow * (AK * 2) + lchk * 16);
    const int b_hl  = tid >> 8;
    const int b_row = (tid & 255) >> 2;
    const int b_chk = tid & 3;
    const unsigned b_dst = (unsigned)(2 * A_TILE + b_hl * B_TILE
                                      + b_row * (AK * 2) + b_chk * 16);
    const __nv_bfloat16* __restrict__ bsrc = b_hl ? d_Wtl : d_Wth;

    unsigned a_off[2];
    #pragma unroll
    for (int i = 0; i < 2; i++)
        a_off[i] = (unsigned)((wm * 32 + i * 16 + (lane & 15)) * (AK * 2)
                              + (lane >> 4) * 16);
    const unsigned b_off =
        (unsigned)((wn * 16 + ((lane >> 4) << 3) + (lane & 7)) * (AK * 2)
                   + (((lane >> 3) & 1) << 4));

    auto load_stage = [&](int it) {
        const int kb = it * 32;
        const unsigned sb = sbase + (unsigned)((it & 1) * STAGE);
        cp16(sb + a_dst,          &d_ph[(size_t)arow * 256 + kb + lchk * 8], asz);
        cp16(sb + A_TILE + a_dst, &d_pl[(size_t)arow * 256 + kb + lchk * 8], asz);
        cp16(sb + b_dst, &bsrc[(size_t)(n0 + b_row) * 256 + kb + b_chk * 8], 16);
        asm volatile("cp.async.commit_group;");
    };

    load_stage(0);
    load_stage(1);

    #pragma unroll
    for (int it = 0; it < 8; it++) {
        if (it < 6) asm volatile("cp.async.wait_group 1;");
        else        asm volatile("cp.async.wait_group 0;");
        __syncthreads();

        const unsigned sb = sbase + (unsigned)((it & 1) * STAGE);

        #pragma unroll
        for (int kk = 0; kk < 2; kk++) {
            const unsigned kadd = kk * 32;

            unsigned ah[2][4], al[2][4];
            #pragma unroll
            for (int i = 0; i < 2; i++) {
                ldsm_x4(ah[i][0], ah[i][1], ah[i][2], ah[i][3],
                        sb + a_off[i] + kadd);
                ldsm_x4(al[i][0], al[i][1], al[i][2], al[i][3],
                        sb + A_TILE + a_off[i] + kadd);
            }
            unsigned bh[2][2], bl[2][2];
            {
                unsigned r0, r1, r2, r3;
                ldsm_x4(r0, r1, r2, r3, sb + 2 * A_TILE + b_off + kadd);
                bh[0][0] = r0; bh[0][1] = r1; bh[1][0] = r2; bh[1][1] = r3;
                ldsm_x4(r0, r1, r2, r3, sb + 2 * A_TILE + B_TILE + b_off + kadd);
                bl[0][0] = r0; bl[0][1] = r1; bl[1][0] = r2; bl[1][1] = r3;
            }

            #pragma unroll
            for (int i = 0; i < 2; i++)
                #pragma unroll
                for (int j = 0; j < 2; j++) {
                    MMA_BF16(acc[i][j], ah[i], bh[j]);
                    MMA_BF16(acc[i][j], ah[i], bl[j]);
                    MMA_BF16(acc[i][j], al[i], bh[j]);
                }
        }
        __syncthreads();
        if (it + 2 < 8) load_stage(it + 2);
    }

    #pragma unroll
    for (int i = 0; i < 2; i++) {
        #pragma unroll
        for (int rr = 0; rr < 2; rr++) {
            const int mrow = m0 + wm * 32 + i * 16 + g + rr * 8;
            if (mrow < S) {
                const float gs = d_gsum[mrow];
                #pragma unroll
                for (int j = 0; j < 2; j++) {
                    const int n = n0 + wn * 16 + j * 8 + 2 * t;
                    float2 o;
                    o.x = acc[i][j][rr * 2 + 0] + gs * bm[n];
                    o.y = acc[i][j][rr * 2 + 1] + gs * bm[n + 1];
                    *(float2*)&out[(size_t)mrow * 256 + n] = o;
                }
            }
        }
    }
}

// ---------------------------------------------------------------------------
// Inputs: x, weights, Wg, bg, Wm, bm, p, index, num_segments
// ---------------------------------------------------------------------------
extern "C" void kernel_launch(void* const* d_in, const int* in_sizes, int n_in,
                              void* d_out, int out_size) {
    const float* x     = (const float*)d_in[0];
    const float* wts   = (const float*)d_in[1];
    const float* Wg    = (const float*)d_in[2];
    const float* bg    = (const float*)d_in[3];
    const float* Wm    = (const float*)d_in[4];
    const float* bm    = (const float*)d_in[5];
    const float* p     = (const float*)d_in[6];
    const int*   index = (const int*)d_in[7];

    const int N = in_sizes[7];
    const int S = out_size / 256;
    const int smem_bytes = 2 * STAGE;   // 61440

    cudaFuncSetAttribute(gemm_mma_kernel,
                         cudaFuncAttributeMaxDynamicSharedMemorySize, smem_bytes);

    const int segBlocks = (N / 4 + 256) / 256;

    setup_kernel<<<segBlocks + 64, 256>>>(index, Wm, N, S, segBlocks);
    pool_kernel<<<(S + 3) / 4, 128>>>(x, wts, Wg, bg, p, S);
    gemm_mma_kernel<<<dim3((S + GM - 1) / GM, 256 / GN), 512, smem_bytes>>>(
        bm, (float*)d_out, S);
}